// round 5
// baseline (speedup 1.0000x reference)
#include <cuda_runtime.h>
#include <math.h>
#include <stdint.h>

// Problem dims (fixed per metadata)
#define B_  16
#define P_  1000
#define N_  1000
#define E_  256
#define HD_ 256
#define H_  16
#define D_  16

// ---------------- scratch (no allocations allowed) ----------------
__device__ float g_K [B_ * N_ * HD_];
__device__ float g_V [B_ * N_ * HD_];
__device__ float g_Q [B_ * P_ * HD_];
__device__ float g_OC[B_ * P_ * HD_];
__device__ float g_MH[B_ * P_ * E_ ];
__device__ float g_S [(size_t)B_ * P_ * N_];   // 64 MB score scratch

#define BM 64
#define BN 64
#define BK 16

// ---------------- generic fp32 GEMM: C[M x Nc] = A[M x 256] @ B[256 x Nc] ----------------
// optional epilogue: + bias[n]  and  + attr[m] * attr_row[n]  (rank-1 for the Q concat column)
__global__ void __launch_bounds__(256)
gemm_k(const float* __restrict__ A, const float* __restrict__ Bw,
       float* __restrict__ C, int Nc,
       const float* __restrict__ bias,
       const float* __restrict__ attr,
       const float* __restrict__ attr_row)
{
    __shared__ float As[BK][BM + 4];
    __shared__ float Bs[BK][BN];
    const int Kdim = 256;
    int tid = threadIdx.x;
    int tx = tid & 15, ty = tid >> 4;
    int m0 = blockIdx.y * BM;
    int n0 = blockIdx.x * BN;
    float acc[4][4] = {};

    for (int k0 = 0; k0 < Kdim; k0 += BK) {
        {   // A tile: 64 rows x 16 k, stored transposed
            int r  = tid >> 2;
            int kq = (tid & 3) * 4;
            float4 a4 = *(const float4*)(A + (size_t)(m0 + r) * Kdim + k0 + kq);
            As[kq + 0][r] = a4.x; As[kq + 1][r] = a4.y;
            As[kq + 2][r] = a4.z; As[kq + 3][r] = a4.w;
        }
        {   // B tile: 16 k x 64 n
            int kk = tid >> 4;
            int c  = (tid & 15) * 4;
            *(float4*)(&Bs[kk][c]) = *(const float4*)(Bw + (size_t)(k0 + kk) * Nc + n0 + c);
        }
        __syncthreads();
#pragma unroll
        for (int k = 0; k < BK; k++) {
            float4 a4 = *(const float4*)(&As[k][ty * 4]);
            float4 b4 = *(const float4*)(&Bs[k][tx * 4]);
            float av[4] = {a4.x, a4.y, a4.z, a4.w};
            float bv[4] = {b4.x, b4.y, b4.z, b4.w};
#pragma unroll
            for (int i = 0; i < 4; i++)
#pragma unroll
                for (int j = 0; j < 4; j++)
                    acc[i][j] = fmaf(av[i], bv[j], acc[i][j]);
        }
        __syncthreads();
    }
#pragma unroll
    for (int i = 0; i < 4; i++) {
        int m = m0 + ty * 4 + i;
        float am = attr ? attr[m] : 0.f;
#pragma unroll
        for (int j = 0; j < 4; j++) {
            int n = n0 + tx * 4 + j;
            float v = acc[i][j];
            if (bias)     v += bias[n];
            if (attr)     v += am * attr_row[n];
            C[(size_t)m * Nc + n] = v;
        }
    }
}

// ---------------- fused K+V projection: one A tile feeds two B matrices ----------------
__global__ void __launch_bounds__(256)
gemm_kv(const float* __restrict__ A, const float* __restrict__ Bk,
        const float* __restrict__ Bv, float* __restrict__ Ck,
        float* __restrict__ Cv)
{
    __shared__ float As [BK][BM + 4];
    __shared__ float Bks[BK][BN];
    __shared__ float Bvs[BK][BN];
    const int Kdim = 256, Nc = HD_;
    int tid = threadIdx.x;
    int tx = tid & 15, ty = tid >> 4;
    int m0 = blockIdx.y * BM;
    int n0 = blockIdx.x * BN;
    float ak[4][4] = {}, av_[4][4] = {};

    for (int k0 = 0; k0 < Kdim; k0 += BK) {
        {
            int r  = tid >> 2;
            int kq = (tid & 3) * 4;
            float4 a4 = *(const float4*)(A + (size_t)(m0 + r) * Kdim + k0 + kq);
            As[kq + 0][r] = a4.x; As[kq + 1][r] = a4.y;
            As[kq + 2][r] = a4.z; As[kq + 3][r] = a4.w;
        }
        {
            int kk = tid >> 4;
            int c  = (tid & 15) * 4;
            *(float4*)(&Bks[kk][c]) = *(const float4*)(Bk + (size_t)(k0 + kk) * Nc + n0 + c);
            *(float4*)(&Bvs[kk][c]) = *(const float4*)(Bv + (size_t)(k0 + kk) * Nc + n0 + c);
        }
        __syncthreads();
#pragma unroll
        for (int k = 0; k < BK; k++) {
            float4 a4 = *(const float4*)(&As[k][ty * 4]);
            float4 bk4 = *(const float4*)(&Bks[k][tx * 4]);
            float4 bv4 = *(const float4*)(&Bvs[k][tx * 4]);
            float a[4]  = {a4.x, a4.y, a4.z, a4.w};
            float bk_[4] = {bk4.x, bk4.y, bk4.z, bk4.w};
            float bv_[4] = {bv4.x, bv4.y, bv4.z, bv4.w};
#pragma unroll
            for (int i = 0; i < 4; i++)
#pragma unroll
                for (int j = 0; j < 4; j++) {
                    ak[i][j]  = fmaf(a[i], bk_[j], ak[i][j]);
                    av_[i][j] = fmaf(a[i], bv_[j], av_[i][j]);
                }
        }
        __syncthreads();
    }
#pragma unroll
    for (int i = 0; i < 4; i++) {
        int m = m0 + ty * 4 + i;
#pragma unroll
        for (int j = 0; j < 4; j++) {
            int n = n0 + tx * 4 + j;
            Ck[(size_t)m * Nc + n] = ak[i][j];
            Cv[(size_t)m * Nc + n] = av_[i][j];
        }
    }
}

// ---------------- fused multi-head attention (flash style, 2 p-rows / thread) ----------------
// block = (b, tile of 32 p).  thread t: h = t>>4, serves p0+(t&15) and p0+(t&15)+16.
// Each K/V float4 smem read feeds two dot products -> higher FMA issue efficiency.
#define ACH 16

__global__ void __launch_bounds__(256)
attn_k(const float* __restrict__ Q, const float* __restrict__ K,
       const float* __restrict__ V, const float* __restrict__ mask,
       float* __restrict__ OC)
{
    extern __shared__ float sm[];
    float* k_sm = sm;                          // ACH * 256
    float* v_sm = k_sm + ACH * HD_;            // ACH * 256
    float* m_sm = v_sm + ACH * HD_;            // 32 * (ACH+1)

    int b  = blockIdx.y;
    int p0 = blockIdx.x * 32;
    int t  = threadIdx.x;
    int h  = t >> 4;
    int pl = t & 15;
    int pa = p0 + pl;
    int pb = p0 + pl + 16;
    bool va = (pa < P_), vb = (pb < P_);

    float4 qa[4], qb[4];
    {
        const float4* qpa = (const float4*)(Q + ((size_t)b * P_ + (va ? pa : 0)) * HD_ + h * D_);
        const float4* qpb = (const float4*)(Q + ((size_t)b * P_ + (vb ? pb : 0)) * HD_ + h * D_);
#pragma unroll
        for (int i = 0; i < 4; i++) {
            qa[i] = va ? qpa[i] : make_float4(0.f, 0.f, 0.f, 0.f);
            qb[i] = vb ? qpb[i] : make_float4(0.f, 0.f, 0.f, 0.f);
        }
    }

    float ma = -INFINITY, sa = 0.f;
    float mb = -INFINITY, sb = 0.f;
    float4 oa[4] = {}, ob[4] = {};

    for (int n0 = 0; n0 < N_; n0 += ACH) {
        int nn = min(ACH, N_ - n0);            // tail: 1000 = 62*16 + 8
        {   // cooperative K/V chunk load
            const float4* Kg = (const float4*)(K + ((size_t)b * N_ + n0) * HD_);
            const float4* Vg = (const float4*)(V + ((size_t)b * N_ + n0) * HD_);
            float4* k4 = (float4*)k_sm;
            float4* v4 = (float4*)v_sm;
            int tot = nn * (HD_ / 4);
            for (int i = t; i < tot; i += 256) { k4[i] = Kg[i]; v4[i] = Vg[i]; }
            // mask chunk: 32 p-rows x ACH n, padded stride
            for (int i = t; i < 32 * ACH; i += 256) {
                int r = i >> 4, c = i & (ACH - 1);
                float mv = 0.f;
                if (p0 + r < P_ && c < nn)
                    mv = mask[((size_t)b * P_ + p0 + r) * N_ + n0 + c];
                m_sm[r * (ACH + 1) + c] = mv;
            }
        }
        __syncthreads();

        float sca[ACH], scb[ACH];
        float cma = -INFINITY, cmb = -INFINITY;
#pragma unroll
        for (int j = 0; j < ACH; j++) {
            const float4* kp = (const float4*)(k_sm + j * HD_ + h * D_);
            float4 k0v = kp[0], k1v = kp[1], k2v = kp[2], k3v = kp[3];
            float ca, cb;
            ca  = qa[0].x * k0v.x + qa[0].y * k0v.y + qa[0].z * k0v.z + qa[0].w * k0v.w;
            ca += qa[1].x * k1v.x + qa[1].y * k1v.y + qa[1].z * k1v.z + qa[1].w * k1v.w;
            ca += qa[2].x * k2v.x + qa[2].y * k2v.y + qa[2].z * k2v.z + qa[2].w * k2v.w;
            ca += qa[3].x * k3v.x + qa[3].y * k3v.y + qa[3].z * k3v.z + qa[3].w * k3v.w;
            cb  = qb[0].x * k0v.x + qb[0].y * k0v.y + qb[0].z * k0v.z + qb[0].w * k0v.w;
            cb += qb[1].x * k1v.x + qb[1].y * k1v.y + qb[1].z * k1v.z + qb[1].w * k1v.w;
            cb += qb[2].x * k2v.x + qb[2].y * k2v.y + qb[2].z * k2v.z + qb[2].w * k2v.w;
            cb += qb[3].x * k3v.x + qb[3].y * k3v.y + qb[3].z * k3v.z + qb[3].w * k3v.w;
            ca = ca * 0.25f + m_sm[pl * (ACH + 1) + j];
            cb = cb * 0.25f + m_sm[(pl + 16) * (ACH + 1) + j];
            sca[j] = (j < nn) ? ca : -INFINITY;
            scb[j] = (j < nn) ? cb : -INFINITY;
            cma = fmaxf(cma, sca[j]);
            cmb = fmaxf(cmb, scb[j]);
        }
        float mna = fmaxf(ma, cma), mnb = fmaxf(mb, cmb);
        float fa = __expf(ma - mna), fb = __expf(mb - mnb);
        sa *= fa; sb *= fb;
#pragma unroll
        for (int i = 0; i < 4; i++) {
            oa[i].x *= fa; oa[i].y *= fa; oa[i].z *= fa; oa[i].w *= fa;
            ob[i].x *= fb; ob[i].y *= fb; ob[i].z *= fb; ob[i].w *= fb;
        }
#pragma unroll
        for (int j = 0; j < ACH; j++) {
            float wa = __expf(sca[j] - mna);
            float wb = __expf(scb[j] - mnb);
            sa += wa; sb += wb;
            const float4* vp = (const float4*)(v_sm + j * HD_ + h * D_);
            float4 v0 = vp[0], v1 = vp[1], v2 = vp[2], v3 = vp[3];
            oa[0].x += wa * v0.x; oa[0].y += wa * v0.y; oa[0].z += wa * v0.z; oa[0].w += wa * v0.w;
            oa[1].x += wa * v1.x; oa[1].y += wa * v1.y; oa[1].z += wa * v1.z; oa[1].w += wa * v1.w;
            oa[2].x += wa * v2.x; oa[2].y += wa * v2.y; oa[2].z += wa * v2.z; oa[2].w += wa * v2.w;
            oa[3].x += wa * v3.x; oa[3].y += wa * v3.y; oa[3].z += wa * v3.z; oa[3].w += wa * v3.w;
            ob[0].x += wb * v0.x; ob[0].y += wb * v0.y; ob[0].z += wb * v0.z; ob[0].w += wb * v0.w;
            ob[1].x += wb * v1.x; ob[1].y += wb * v1.y; ob[1].z += wb * v1.z; ob[1].w += wb * v1.w;
            ob[2].x += wb * v2.x; ob[2].y += wb * v2.y; ob[2].z += wb * v2.z; ob[2].w += wb * v2.w;
            ob[3].x += wb * v3.x; ob[3].y += wb * v3.y; ob[3].z += wb * v3.z; ob[3].w += wb * v3.w;
        }
        ma = mna; mb = mnb;
        __syncthreads();
    }

    if (va) {
        float inv = 1.f / sa;
        float4* op = (float4*)(OC + ((size_t)b * P_ + pa) * HD_ + h * D_);
#pragma unroll
        for (int i = 0; i < 4; i++) {
            float4 o = oa[i];
            o.x *= inv; o.y *= inv; o.z *= inv; o.w *= inv;
            op[i] = o;
        }
    }
    if (vb) {
        float inv = 1.f / sb;
        float4* op = (float4*)(OC + ((size_t)b * P_ + pb) * HD_ + h * D_);
#pragma unroll
        for (int i = 0; i < 4; i++) {
            float4 o = ob[i];
            o.x *= inv; o.y *= inv; o.z *= inv; o.w *= inv;
            op[i] = o;
        }
    }
}

// ---------------- probe score GEMM: S[b] = 10*tanh((MH[b] @ enc[b]^T)/16) + mask[b] ----------------
__global__ void __launch_bounds__(256)
gemm_abT(const float* __restrict__ MH, const float* __restrict__ enc,
         const float* __restrict__ mask, float* __restrict__ S)
{
    __shared__ float As[BK][BM + 4];
    __shared__ float Bs[BK][BN + 4];
    const int Kdim = 256;
    int b  = blockIdx.z;
    int tid = threadIdx.x;
    int tx = tid & 15, ty = tid >> 4;
    int m0 = blockIdx.y * BM;
    int n0 = blockIdx.x * BN;

    const float* A  = MH  + (size_t)b * P_ * E_;
    const float* Bm = enc + (size_t)b * N_ * E_;
    float acc[4][4] = {};

    for (int k0 = 0; k0 < Kdim; k0 += BK) {
        int r  = tid >> 2;
        int kq = (tid & 3) * 4;
        {   // A tile (row clamp for the 1000 = 15*64+40 tail)
            int m = m0 + r; if (m >= P_) m = P_ - 1;
            float4 a4 = *(const float4*)(A + (size_t)m * Kdim + k0 + kq);
            As[kq + 0][r] = a4.x; As[kq + 1][r] = a4.y;
            As[kq + 2][r] = a4.z; As[kq + 3][r] = a4.w;
        }
        {   // B tile (rows are n-dim)
            int n = n0 + r; if (n >= N_) n = N_ - 1;
            float4 b4 = *(const float4*)(Bm + (size_t)n * Kdim + k0 + kq);
            Bs[kq + 0][r] = b4.x; Bs[kq + 1][r] = b4.y;
            Bs[kq + 2][r] = b4.z; Bs[kq + 3][r] = b4.w;
        }
        __syncthreads();
#pragma unroll
        for (int k = 0; k < BK; k++) {
            float4 a4 = *(const float4*)(&As[k][ty * 4]);
            float4 b4 = *(const float4*)(&Bs[k][tx * 4]);
            float av[4] = {a4.x, a4.y, a4.z, a4.w};
            float bv[4] = {b4.x, b4.y, b4.z, b4.w};
#pragma unroll
            for (int i = 0; i < 4; i++)
#pragma unroll
                for (int j = 0; j < 4; j++)
                    acc[i][j] = fmaf(av[i], bv[j], acc[i][j]);
        }
        __syncthreads();
    }
#pragma unroll
    for (int i = 0; i < 4; i++) {
        int m = m0 + ty * 4 + i;
        if (m >= P_) continue;
#pragma unroll
        for (int j = 0; j < 4; j++) {
            int n = n0 + tx * 4 + j;
            if (n >= N_) continue;
            size_t idx = ((size_t)b * P_ + m) * N_ + n;
            S[idx] = 10.f * tanhf(acc[i][j] * 0.0625f) + mask[idx];
        }
    }
}

// ---------------- row softmax over S: one block per row ----------------
__global__ void __launch_bounds__(256)
softmax_k(const float* __restrict__ S, float* __restrict__ out)
{
    __shared__ float red[8];
    size_t row = blockIdx.x;                  // 0 .. B_*P_-1
    const float* src = S   + row * N_;
    float*       dst = out + row * N_;
    int t = threadIdx.x;
    int lane = t & 31, w = t >> 5;

    float v[4];
    float lm = -INFINITY;
#pragma unroll
    for (int i = 0; i < 4; i++) {
        int n = t + i * 256;
        v[i] = (n < N_) ? src[n] : -INFINITY;
        lm = fmaxf(lm, v[i]);
    }
#pragma unroll
    for (int o = 16; o; o >>= 1) lm = fmaxf(lm, __shfl_xor_sync(~0u, lm, o));
    if (lane == 0) red[w] = lm;
    __syncthreads();
    lm = red[lane & 7];
#pragma unroll
    for (int o = 4; o; o >>= 1) lm = fmaxf(lm, __shfl_xor_sync(~0u, lm, o));
    float M = lm;

    float ls = 0.f;
#pragma unroll
    for (int i = 0; i < 4; i++) {
        v[i] = __expf(v[i] - M);
        ls += v[i];
    }
#pragma unroll
    for (int o = 16; o; o >>= 1) ls += __shfl_xor_sync(~0u, ls, o);
    __syncthreads();
    if (lane == 0) red[w] = ls;
    __syncthreads();
    ls = red[lane & 7];
#pragma unroll
    for (int o = 4; o; o >>= 1) ls += __shfl_xor_sync(~0u, ls, o);
    float inv = 1.f / ls;

#pragma unroll
    for (int i = 0; i < 4; i++) {
        int n = t + i * 256;
        if (n < N_) dst[n] = v[i] * inv;
    }
}

// ---------------- launch ----------------
static const int ATTN_SMEM = (ACH * HD_ * 2 + 32 * (ACH + 1)) * (int)sizeof(float);

extern "C" void kernel_launch(void* const* d_in, const int* in_sizes, int n_in,
                              void* d_out, int out_size)
{
    const float* eln  = (const float*)d_in[0];
    const float* attr = (const float*)d_in[1];
    const float* mask = (const float*)d_in[2];
    const float* enc  = (const float*)d_in[3];
    const float* Wq   = (const float*)d_in[4];  // [257, 256]
    const float* Wk   = (const float*)d_in[5];
    const float* Wv   = (const float*)d_in[6];
    const float* Wc   = (const float*)d_in[7];
    const float* bc   = (const float*)d_in[8];
    float* out = (float*)d_out;

    float *Kp, *Vp, *Qp, *OCp, *MHp, *Sp;
    cudaGetSymbolAddress((void**)&Kp,  g_K);
    cudaGetSymbolAddress((void**)&Vp,  g_V);
    cudaGetSymbolAddress((void**)&Qp,  g_Q);
    cudaGetSymbolAddress((void**)&OCp, g_OC);
    cudaGetSymbolAddress((void**)&MHp, g_MH);
    cudaGetSymbolAddress((void**)&Sp,  g_S);

    cudaFuncSetAttribute(attn_k, cudaFuncAttributeMaxDynamicSharedMemorySize, ATTN_SMEM);

    dim3 gg(HD_ / BN, (B_ * N_) / BM);   // (4, 250)

    // K,V projections fused (shared A tiles), Q projection with rank-1 attr column
    gemm_kv<<<gg, 256>>>(enc, Wk, Wv, Kp, Vp);
    gemm_k <<<gg, 256>>>(eln, Wq, Qp, HD_, nullptr, attr, Wq + 256 * 256);

    // fused MHA (32 p per block, 2 p per thread)
    attn_k<<<dim3((P_ + 31) / 32, B_), 256, ATTN_SMEM>>>(Qp, Kp, Vp, mask, OCp);

    // output projection
    gemm_k<<<gg, 256>>>(OCp, Wc, MHp, E_, bc, nullptr, nullptr);

    // probe score GEMM (+ tanh/mask epilogue) then row softmax
    dim3 gp((N_ + BN - 1) / BN, (P_ + BM - 1) / BM, B_);   // (16, 16, 16)
    gemm_abT <<<gp, 256>>>(MHp, enc, mask, Sp);
    softmax_k<<<B_ * P_, 256>>>(Sp, out);
}